// round 1
// baseline (speedup 1.0000x reference)
#include <cuda_runtime.h>
#include <cuda_bf16.h>

#define N_NODES 65536
#define N_EDGES 1048576
#define HDIM    128
#define IN_F    5
#define N_GRAPH 16
#define ELEC    32
#define BSZ     128
#define LCONV   63   // (128-3)/2+1

// ---------------- device scratch (no allocations allowed) ----------------
__device__ float g_h  [N_NODES * HDIM];     // 32 MB
__device__ float g_m  [N_NODES * HDIM];     // 32 MB
__device__ float g_agg[N_NODES * HDIM];     // 32 MB
__device__ float g_gi [N_NODES * 3 * HDIM]; // 96 MB
__device__ float g_gh [N_NODES * 3 * HDIM]; // 96 MB
__device__ float g_wT [2 * HDIM * 3 * HDIM]; // w_ih^T, w_hh^T  [128][384] each

// ---------------- small helpers ----------------
__global__ void zero_kernel(float4* p, int n4) {
    int i = blockIdx.x * blockDim.x + threadIdx.x;
    if (i < n4) p[i] = make_float4(0.f, 0.f, 0.f, 0.f);
}

// h[:, 0:5] = x, rest 0
__global__ void pad_kernel(const float* __restrict__ x, float* __restrict__ h) {
    int i = blockIdx.x * blockDim.x + threadIdx.x;   // over N*32 float4s
    if (i >= N_NODES * 32) return;
    int n = i >> 5, c4 = i & 31;
    float4 v = make_float4(0.f, 0.f, 0.f, 0.f);
    if (c4 == 0) {
        const float* xr = x + n * IN_F;
        v.x = xr[0]; v.y = xr[1]; v.z = xr[2]; v.w = xr[3];
    } else if (c4 == 1) {
        v.x = x[n * IN_F + 4];
    }
    reinterpret_cast<float4*>(h)[i] = v;
}

// wT[k][j] = w[j][k]  for both gru weight matrices ([384][128] -> [128][384])
__global__ void transpose_w_kernel(const float* __restrict__ w_ih,
                                   const float* __restrict__ w_hh,
                                   float* __restrict__ wT) {
    int idx = blockIdx.x * blockDim.x + threadIdx.x;
    if (idx >= 384 * 128) return;
    int j = idx / 128, k = idx % 128;
    wT[k * 384 + j]              = w_ih[idx];
    wT[49152 + k * 384 + j]      = w_hh[idx];
}

// ---------------- fp32 GEMM: C[M,Nc] = A[M,128] @ B[128,Nc] (+bias) ----------------
// Block tile: 64 rows x 128 cols, 256 threads, 4x8 microtile. K = 128 fixed.
#define AS_STRIDE 132
#define BS_STRIDE 136
#define GEMM_SMEM ((64 * AS_STRIDE + 128 * BS_STRIDE) * 4)

__global__ void gemm_k128(const float* __restrict__ A, const float* __restrict__ B,
                          const float* __restrict__ bias, float* __restrict__ C,
                          int Nc) {
    extern __shared__ float sm[];
    float* As = sm;                       // [64][AS_STRIDE], row-major (r, k)
    float* Bs = sm + 64 * AS_STRIDE;      // [128][BS_STRIDE], (k, c)

    int t  = threadIdx.x;
    int rb = blockIdx.x * 64;
    int cb = blockIdx.y * 128;
    int tx = t & 15;        // col group: 8 cols
    int ty = t >> 4;        // row group: 4 rows

    // load A tile (64 x 128), coalesced float4, conflict-free stores
    const float4* A4 = reinterpret_cast<const float4*>(A);
    #pragma unroll
    for (int i = t; i < 64 * 32; i += 256) {
        int r = i >> 5, k4 = i & 31;
        float4 v = A4[(size_t)(rb + r) * 32 + k4];
        *reinterpret_cast<float4*>(&As[r * AS_STRIDE + 4 * k4]) = v;
    }
    // load B tile (128 x 128 cols of this block)
    #pragma unroll
    for (int i = t; i < 128 * 32; i += 256) {
        int k = i >> 5, c4 = i & 31;
        float4 v = *reinterpret_cast<const float4*>(&B[(size_t)k * Nc + cb + 4 * c4]);
        *reinterpret_cast<float4*>(&Bs[k * BS_STRIDE + 4 * c4]) = v;
    }
    __syncthreads();

    float acc[4][8];
    #pragma unroll
    for (int i = 0; i < 4; i++)
        #pragma unroll
        for (int j = 0; j < 8; j++) acc[i][j] = 0.f;

    const float* a0 = &As[(ty * 4 + 0) * AS_STRIDE];
    const float* a1 = &As[(ty * 4 + 1) * AS_STRIDE];
    const float* a2 = &As[(ty * 4 + 2) * AS_STRIDE];
    const float* a3 = &As[(ty * 4 + 3) * AS_STRIDE];

    #pragma unroll 8
    for (int k = 0; k < 128; k++) {
        float4 b0 = *reinterpret_cast<const float4*>(&Bs[k * BS_STRIDE + tx * 8]);
        float4 b1 = *reinterpret_cast<const float4*>(&Bs[k * BS_STRIDE + tx * 8 + 4]);
        float av[4] = {a0[k], a1[k], a2[k], a3[k]};
        #pragma unroll
        for (int i = 0; i < 4; i++) {
            acc[i][0] += av[i] * b0.x; acc[i][1] += av[i] * b0.y;
            acc[i][2] += av[i] * b0.z; acc[i][3] += av[i] * b0.w;
            acc[i][4] += av[i] * b1.x; acc[i][5] += av[i] * b1.y;
            acc[i][6] += av[i] * b1.z; acc[i][7] += av[i] * b1.w;
        }
    }

    float bv[8];
    #pragma unroll
    for (int j = 0; j < 8; j++) bv[j] = bias ? bias[cb + tx * 8 + j] : 0.f;

    #pragma unroll
    for (int i = 0; i < 4; i++) {
        int r = rb + ty * 4 + i;
        float* crow = C + (size_t)r * Nc + cb + tx * 8;
        float4 o0, o1;
        o0.x = acc[i][0] + bv[0]; o0.y = acc[i][1] + bv[1];
        o0.z = acc[i][2] + bv[2]; o0.w = acc[i][3] + bv[3];
        o1.x = acc[i][4] + bv[4]; o1.y = acc[i][5] + bv[5];
        o1.z = acc[i][6] + bv[6]; o1.w = acc[i][7] + bv[7];
        *reinterpret_cast<float4*>(crow)     = o0;
        *reinterpret_cast<float4*>(crow + 4) = o1;
    }
}

// ---------------- edge scatter: agg[dst] += m[src] * ea ----------------
__global__ void scatter_kernel(const int* __restrict__ ei, const float* __restrict__ ea,
                               const float* __restrict__ m, float* __restrict__ agg) {
    int gid  = blockIdx.x * blockDim.x + threadIdx.x;
    int e    = gid >> 5;
    int lane = gid & 31;
    if (e >= N_EDGES) return;
    int   s = __ldg(ei + e);
    int   d = __ldg(ei + N_EDGES + e);
    float w = __ldg(ea + e);
    float4 v = reinterpret_cast<const float4*>(m + (size_t)s * HDIM)[lane];
    v.x *= w; v.y *= w; v.z *= w; v.w *= w;
    float* dst = agg + (size_t)d * HDIM + lane * 4;
    asm volatile("red.global.add.v4.f32 [%0], {%1, %2, %3, %4};"
                 :: "l"(dst), "f"(v.x), "f"(v.y), "f"(v.z), "f"(v.w) : "memory");
}

// ---------------- GRU elementwise update (h in place) ----------------
__global__ void gru_kernel(const float* __restrict__ gi, const float* __restrict__ gh,
                           float* __restrict__ h) {
    int idx = blockIdx.x * blockDim.x + threadIdx.x;   // N*128
    if (idx >= N_NODES * HDIM) return;
    int n = idx >> 7, c = idx & 127;
    int base = n * 384 + c;
    float ir = gi[base], iz = gi[base + 128], in_ = gi[base + 256];
    float hr = gh[base], hz = gh[base + 128], hn  = gh[base + 256];
    float hold = h[idx];
    float r  = 1.f / (1.f + __expf(-(ir + hr)));
    float z  = 1.f / (1.f + __expf(-(iz + hz)));
    float nn = tanhf(in_ + r * hn);
    h[idx] = (1.f - z) * nn + z * hold;
}

// ---------------- post: relu -> conv1d(stride2) -> relu -> lin1 -> relu -> lin2 -> softmax ----
__global__ void post_kernel(const float* __restrict__ h,
                            const float* __restrict__ conv_w, const float* __restrict__ conv_b,
                            const float* __restrict__ lin1_w, const float* __restrict__ lin1_b,
                            const float* __restrict__ lin2_w, const float* __restrict__ lin2_b,
                            float* __restrict__ out) {
    int b = blockIdx.x;      // 0..127
    int t = threadIdx.x;     // 256
    __shared__ float cw[48];
    __shared__ float v[ELEC * LCONV];   // 2016
    __shared__ float u[HDIM];

    if (t < 48) cw[t] = conv_w[t];
    __syncthreads();
    float cb0 = conv_b[0];

    // conv over g-channels; input = relu(h)
    for (int idx = t; idx < ELEC * LCONV; idx += 256) {
        int e = idx / LCONV, l = idx % LCONV;
        float s = cb0;
        #pragma unroll
        for (int g = 0; g < N_GRAPH; g++) {
            const float* hr = h + ((size_t)((b * N_GRAPH + g) * ELEC + e)) * HDIM + 2 * l;
            s += cw[g * 3 + 0] * fmaxf(hr[0], 0.f)
               + cw[g * 3 + 1] * fmaxf(hr[1], 0.f)
               + cw[g * 3 + 2] * fmaxf(hr[2], 0.f);
        }
        v[idx] = fmaxf(s, 0.f);
    }
    __syncthreads();

    // lin1: 128 outputs, warp-per-output dot over 2016
    int w = t >> 5, lane = t & 31;
    for (int j = w; j < HDIM; j += 8) {
        float s = 0.f;
        for (int f = lane * 4; f < ELEC * LCONV; f += 128) {
            float4 wv = *reinterpret_cast<const float4*>(&lin1_w[(size_t)j * 2016 + f]);
            float4 vv = *reinterpret_cast<const float4*>(&v[f]);
            s += wv.x * vv.x + wv.y * vv.y + wv.z * vv.z + wv.w * vv.w;
        }
        #pragma unroll
        for (int o = 16; o; o >>= 1) s += __shfl_xor_sync(0xffffffffu, s, o);
        if (lane == 0) u[j] = fmaxf(s + lin1_b[j], 0.f);
    }
    __syncthreads();

    // lin2 + softmax (warp 0)
    if (t < 32) {
        float s3[3];
        #pragma unroll
        for (int j = 0; j < 3; j++) {
            float acc = 0.f;
            for (int f = t; f < HDIM; f += 32) acc += lin2_w[j * HDIM + f] * u[f];
            #pragma unroll
            for (int o = 16; o; o >>= 1) acc += __shfl_xor_sync(0xffffffffu, acc, o);
            s3[j] = acc + lin2_b[j];
        }
        if (t == 0) {
            float mx = fmaxf(s3[0], fmaxf(s3[1], s3[2]));
            float e0 = expf(s3[0] - mx), e1 = expf(s3[1] - mx), e2 = expf(s3[2] - mx);
            float inv = 1.f / (e0 + e1 + e2);
            out[b * 3 + 0] = e0 * inv;
            out[b * 3 + 1] = e1 * inv;
            out[b * 3 + 2] = e2 * inv;
        }
    }
}

// ---------------- launch ----------------
extern "C" void kernel_launch(void* const* d_in, const int* in_sizes, int n_in,
                              void* d_out, int out_size) {
    const float* x       = (const float*)d_in[0];
    const int*   ei      = (const int*)  d_in[1];
    const float* ea      = (const float*)d_in[2];
    // d_in[3] = bs (constant 128, hardcoded)
    const float* gconv_w = (const float*)d_in[4];
    const float* w_ih    = (const float*)d_in[5];
    const float* w_hh    = (const float*)d_in[6];
    const float* b_ih    = (const float*)d_in[7];
    const float* b_hh    = (const float*)d_in[8];
    const float* conv_w  = (const float*)d_in[9];
    const float* conv_b  = (const float*)d_in[10];
    const float* lin1_w  = (const float*)d_in[11];
    const float* lin1_b  = (const float*)d_in[12];
    const float* lin2_w  = (const float*)d_in[13];
    const float* lin2_b  = (const float*)d_in[14];
    float* out = (float*)d_out;

    float *ph, *pm, *pagg, *pgi, *pgh, *pwT;
    cudaGetSymbolAddress((void**)&ph,   g_h);
    cudaGetSymbolAddress((void**)&pm,   g_m);
    cudaGetSymbolAddress((void**)&pagg, g_agg);
    cudaGetSymbolAddress((void**)&pgi,  g_gi);
    cudaGetSymbolAddress((void**)&pgh,  g_gh);
    cudaGetSymbolAddress((void**)&pwT,  g_wT);

    cudaFuncSetAttribute(gemm_k128, cudaFuncAttributeMaxDynamicSharedMemorySize, GEMM_SMEM);

    transpose_w_kernel<<<(384 * 128 + 255) / 256, 256>>>(w_ih, w_hh, pwT);
    pad_kernel<<<(N_NODES * 32 + 255) / 256, 256>>>(x, ph);

    for (int layer = 0; layer < 2; layer++) {
        // m = h @ gconv_w[layer]
        gemm_k128<<<dim3(N_NODES / 64, 1), 256, GEMM_SMEM>>>(
            ph, gconv_w + (size_t)layer * HDIM * HDIM, nullptr, pm, HDIM);
        // agg = 0
        zero_kernel<<<(N_NODES * 32 + 255) / 256, 256>>>((float4*)pagg, N_NODES * 32);
        // agg[dst] += m[src] * ea
        scatter_kernel<<<(N_EDGES * 32) / 256, 256>>>(ei, ea, pm, pagg);
        // gi = agg @ w_ih^T + b_ih ; gh = h @ w_hh^T + b_hh
        gemm_k128<<<dim3(N_NODES / 64, 3), 256, GEMM_SMEM>>>(pagg, pwT,          b_ih, pgi, 384);
        gemm_k128<<<dim3(N_NODES / 64, 3), 256, GEMM_SMEM>>>(ph,   pwT + 49152,  b_hh, pgh, 384);
        // GRU update
        gru_kernel<<<(N_NODES * HDIM + 255) / 256, 256>>>(pgi, pgh, ph);
    }

    post_kernel<<<BSZ, 256>>>(ph, conv_w, conv_b, lin1_w, lin1_b, lin2_w, lin2_b, out);
}

// round 3
// speedup vs baseline: 1.9708x; 1.9708x over previous
#include <cuda_runtime.h>
#include <cuda_bf16.h>
#include <cstdint>

#define N_NODES 65536
#define N_EDGES 1048576
#define HDIM    128
#define IN_F    5
#define N_GRAPH 16
#define ELEC    32
#define BSZ     128
#define LCONV   63   // (128-3)/2+1

// ---------------- device scratch (no allocations allowed) ----------------
__device__ float g_h  [N_NODES * HDIM];     // 32 MB
__device__ float g_m  [N_NODES * HDIM];     // 32 MB
__device__ float g_agg[N_NODES * HDIM];     // 32 MB
__device__ float g_gi [N_NODES * 3 * HDIM]; // 96 MB
__device__ float g_gh [N_NODES * 3 * HDIM]; // 96 MB
__device__ float g_wT [2 * HDIM * HDIM];    // transposed gconv weights [2][n][k]

// ---------------- helpers ----------------
__device__ __forceinline__ unsigned int f2tf(float f) {
    unsigned int u; asm("cvt.rna.tf32.f32 %0, %1;" : "=r"(u) : "f"(f)); return u;
}

__device__ __forceinline__ void mma_tf32(float* c, const unsigned int* a, const unsigned int* b) {
    asm("mma.sync.aligned.m16n8k8.row.col.f32.tf32.tf32.f32 "
        "{%0,%1,%2,%3},{%4,%5,%6,%7},{%8,%9},{%0,%1,%2,%3};"
        : "+f"(c[0]), "+f"(c[1]), "+f"(c[2]), "+f"(c[3])
        : "r"(a[0]), "r"(a[1]), "r"(a[2]), "r"(a[3]), "r"(b[0]), "r"(b[1]));
}

__global__ void zero_kernel(float4* p, int n4) {
    int i = blockIdx.x * blockDim.x + threadIdx.x;
    if (i < n4) p[i] = make_float4(0.f, 0.f, 0.f, 0.f);
}

// h[:, 0:5] = x, rest 0
__global__ void pad_kernel(const float* __restrict__ x, float* __restrict__ h) {
    int i = blockIdx.x * blockDim.x + threadIdx.x;   // over N*32 float4s
    if (i >= N_NODES * 32) return;
    int n = i >> 5, c4 = i & 31;
    float4 v = make_float4(0.f, 0.f, 0.f, 0.f);
    if (c4 == 0) {
        const float* xr = x + n * IN_F;
        v.x = xr[0]; v.y = xr[1]; v.z = xr[2]; v.w = xr[3];
    } else if (c4 == 1) {
        v.x = x[n * IN_F + 4];
    }
    reinterpret_cast<float4*>(h)[i] = v;
}

// wT[l][n][k] = gconv_w[l][k][n]  (so GEMM B operand is always [N,K] K-major)
__global__ void prep_gconv(const float* __restrict__ w, float* __restrict__ wT) {
    int idx = blockIdx.x * blockDim.x + threadIdx.x;
    if (idx >= 2 * HDIM * HDIM) return;
    int l = idx >> 14, rem = idx & 16383, n = rem >> 7, k = rem & 127;
    wT[l * 16384 + n * 128 + k] = w[l * 16384 + k * 128 + n];
}

// ---------------- tf32 tensor-core GEMM ----------------
// C[M,Nc] = A[M,128] @ Bsrc^T  where Bsrc is [Nc,128] row-major (K-major).
// Block tile 128x128, full K=128 in smem, 8 warps (2x4), warp tile 64x32.
#define AS_STR 132
#define BS_STR 136
#define GEMM_SMEM ((128 * AS_STR + 128 * BS_STR) * 4)

__global__ void gemm_tf32(const float* __restrict__ A, const float* __restrict__ Bsrc,
                          const float* __restrict__ bias, float* __restrict__ C, int Nc) {
    extern __shared__ unsigned int sm[];
    unsigned int* As = sm;                    // [128][AS_STR]
    unsigned int* Bs = sm + 128 * AS_STR;     // [128][BS_STR]

    int t  = threadIdx.x;
    int rb = blockIdx.x * 128;
    int cb = blockIdx.y * 128;

    // load + convert A tile (128 x 128)
    {
        const float4* A4 = reinterpret_cast<const float4*>(A) + (size_t)rb * 32;
        #pragma unroll
        for (int i = t; i < 128 * 32; i += 256) {
            int r = i >> 5, k4 = i & 31;
            float4 v = A4[r * 32 + k4];
            uint4 u = make_uint4(f2tf(v.x), f2tf(v.y), f2tf(v.z), f2tf(v.w));
            *reinterpret_cast<uint4*>(&As[r * AS_STR + k4 * 4]) = u;
        }
    }
    // load + convert B tile: rows cb..cb+127 of Bsrc [Nc][128]
    {
        const float4* B4 = reinterpret_cast<const float4*>(Bsrc) + (size_t)cb * 32;
        #pragma unroll
        for (int i = t; i < 128 * 32; i += 256) {
            int n = i >> 5, k4 = i & 31;
            float4 v = B4[n * 32 + k4];
            uint4 u = make_uint4(f2tf(v.x), f2tf(v.y), f2tf(v.z), f2tf(v.w));
            *reinterpret_cast<uint4*>(&Bs[n * BS_STR + k4 * 4]) = u;
        }
    }
    __syncthreads();

    int warp = t >> 5, lane = t & 31;
    int wm = (warp >> 2) * 64;    // 2 warp-rows of 64
    int wn = (warp & 3) * 32;     // 4 warp-cols of 32
    int lr = lane >> 2, lc = lane & 3;

    float acc[4][4][4];
    #pragma unroll
    for (int mt = 0; mt < 4; mt++)
        #pragma unroll
        for (int nt = 0; nt < 4; nt++)
            #pragma unroll
            for (int q = 0; q < 4; q++) acc[mt][nt][q] = 0.f;

    #pragma unroll
    for (int kk = 0; kk < 16; kk++) {
        int k0 = kk * 8 + lc;
        unsigned int a[4][4], b[4][2];
        #pragma unroll
        for (int mt = 0; mt < 4; mt++) {
            int r = wm + mt * 16 + lr;
            a[mt][0] = As[r * AS_STR + k0];
            a[mt][1] = As[(r + 8) * AS_STR + k0];
            a[mt][2] = As[r * AS_STR + k0 + 4];
            a[mt][3] = As[(r + 8) * AS_STR + k0 + 4];
        }
        #pragma unroll
        for (int nt = 0; nt < 4; nt++) {
            int n = wn + nt * 8 + lr;
            b[nt][0] = Bs[n * BS_STR + k0];
            b[nt][1] = Bs[n * BS_STR + k0 + 4];
        }
        #pragma unroll
        for (int mt = 0; mt < 4; mt++)
            #pragma unroll
            for (int nt = 0; nt < 4; nt++)
                mma_tf32(acc[mt][nt], a[mt], b[nt]);
    }

    // epilogue: bias + store (float2 per fragment row)
    #pragma unroll
    for (int nt = 0; nt < 4; nt++) {
        int c = cb + wn + nt * 8 + lc * 2;
        float b0 = bias ? __ldg(bias + c) : 0.f;
        float b1 = bias ? __ldg(bias + c + 1) : 0.f;
        #pragma unroll
        for (int mt = 0; mt < 4; mt++) {
            int r = rb + wm + mt * 16 + lr;
            float2 v0 = make_float2(acc[mt][nt][0] + b0, acc[mt][nt][1] + b1);
            float2 v1 = make_float2(acc[mt][nt][2] + b0, acc[mt][nt][3] + b1);
            *reinterpret_cast<float2*>(&C[(size_t)r * Nc + c])       = v0;
            *reinterpret_cast<float2*>(&C[(size_t)(r + 8) * Nc + c]) = v1;
        }
    }
}

// ---------------- edge scatter: agg[dst] += m[src] * ea ----------------
__global__ void scatter_kernel(const int* __restrict__ ei, const float* __restrict__ ea,
                               const float* __restrict__ m, float* __restrict__ agg) {
    int gid  = blockIdx.x * blockDim.x + threadIdx.x;
    int e    = gid >> 5;
    int lane = gid & 31;
    if (e >= N_EDGES) return;
    int   s = __ldg(ei + e);
    int   d = __ldg(ei + N_EDGES + e);
    float w = __ldg(ea + e);
    float4 v = reinterpret_cast<const float4*>(m + (size_t)s * HDIM)[lane];
    v.x *= w; v.y *= w; v.z *= w; v.w *= w;
    float* dst = agg + (size_t)d * HDIM + lane * 4;
    asm volatile("red.global.add.v4.f32 [%0], {%1, %2, %3, %4};"
                 :: "l"(dst), "f"(v.x), "f"(v.y), "f"(v.z), "f"(v.w) : "memory");
}

// ---------------- GRU elementwise update (h in place, vectorized) ----------------
__global__ void gru_kernel(const float4* __restrict__ gi, const float4* __restrict__ gh,
                           float4* __restrict__ h) {
    int idx = blockIdx.x * blockDim.x + threadIdx.x;   // N*32 float4s
    if (idx >= N_NODES * 32) return;
    int n = idx >> 5, q = idx & 31;
    const float4* gin = gi + (size_t)n * 96;
    const float4* ghn = gh + (size_t)n * 96;
    float4 ir = gin[q], iz = gin[q + 32], in_ = gin[q + 64];
    float4 hr = ghn[q], hz = ghn[q + 32], hn  = ghn[q + 64];
    float4 ho = h[idx];
    float4 o;
    {
        float r  = 1.f / (1.f + __expf(-(ir.x + hr.x)));
        float z  = 1.f / (1.f + __expf(-(iz.x + hz.x)));
        float nn = tanhf(in_.x + r * hn.x);
        o.x = (1.f - z) * nn + z * ho.x;
    }
    {
        float r  = 1.f / (1.f + __expf(-(ir.y + hr.y)));
        float z  = 1.f / (1.f + __expf(-(iz.y + hz.y)));
        float nn = tanhf(in_.y + r * hn.y);
        o.y = (1.f - z) * nn + z * ho.y;
    }
    {
        float r  = 1.f / (1.f + __expf(-(ir.z + hr.z)));
        float z  = 1.f / (1.f + __expf(-(iz.z + hz.z)));
        float nn = tanhf(in_.z + r * hn.z);
        o.z = (1.f - z) * nn + z * ho.z;
    }
    {
        float r  = 1.f / (1.f + __expf(-(ir.w + hr.w)));
        float z  = 1.f / (1.f + __expf(-(iz.w + hz.w)));
        float nn = tanhf(in_.w + r * hn.w);
        o.w = (1.f - z) * nn + z * ho.w;
    }
    h[idx] = o;
}

// ---------------- post: relu -> conv1d(stride2) -> relu -> lin1 -> relu -> lin2 -> softmax ----
__global__ void post_kernel(const float* __restrict__ h,
                            const float* __restrict__ conv_w, const float* __restrict__ conv_b,
                            const float* __restrict__ lin1_w, const float* __restrict__ lin1_b,
                            const float* __restrict__ lin2_w, const float* __restrict__ lin2_b,
                            float* __restrict__ out) {
    int b = blockIdx.x;      // 0..127
    int t = threadIdx.x;     // 256
    __shared__ float cw[48];
    __shared__ float v[ELEC * LCONV];   // 2016
    __shared__ float u[HDIM];

    if (t < 48) cw[t] = conv_w[t];
    __syncthreads();
    float cb0 = conv_b[0];

    for (int idx = t; idx < ELEC * LCONV; idx += 256) {
        int e = idx / LCONV, l = idx % LCONV;
        float s = cb0;
        #pragma unroll
        for (int g = 0; g < N_GRAPH; g++) {
            const float* hr = h + ((size_t)((b * N_GRAPH + g) * ELEC + e)) * HDIM + 2 * l;
            s += cw[g * 3 + 0] * fmaxf(hr[0], 0.f)
               + cw[g * 3 + 1] * fmaxf(hr[1], 0.f)
               + cw[g * 3 + 2] * fmaxf(hr[2], 0.f);
        }
        v[idx] = fmaxf(s, 0.f);
    }
    __syncthreads();

    int w = t >> 5, lane = t & 31;
    for (int j = w; j < HDIM; j += 8) {
        float s = 0.f;
        for (int f = lane * 4; f < ELEC * LCONV; f += 128) {
            float4 wv = *reinterpret_cast<const float4*>(&lin1_w[(size_t)j * 2016 + f]);
            float4 vv = *reinterpret_cast<const float4*>(&v[f]);
            s += wv.x * vv.x + wv.y * vv.y + wv.z * vv.z + wv.w * vv.w;
        }
        #pragma unroll
        for (int o = 16; o; o >>= 1) s += __shfl_xor_sync(0xffffffffu, s, o);
        if (lane == 0) u[j] = fmaxf(s + lin1_b[j], 0.f);
    }
    __syncthreads();

    if (t < 32) {
        float s3[3];
        #pragma unroll
        for (int j = 0; j < 3; j++) {
            float acc = 0.f;
            for (int f = t; f < HDIM; f += 32) acc += lin2_w[j * HDIM + f] * u[f];
            #pragma unroll
            for (int o = 16; o; o >>= 1) acc += __shfl_xor_sync(0xffffffffu, acc, o);
            s3[j] = acc + lin2_b[j];
        }
        if (t == 0) {
            float mx = fmaxf(s3[0], fmaxf(s3[1], s3[2]));
            float e0 = expf(s3[0] - mx), e1 = expf(s3[1] - mx), e2 = expf(s3[2] - mx);
            float inv = 1.f / (e0 + e1 + e2);
            out[b * 3 + 0] = e0 * inv;
            out[b * 3 + 1] = e1 * inv;
            out[b * 3 + 2] = e2 * inv;
        }
    }
}

// ---------------- launch ----------------
extern "C" void kernel_launch(void* const* d_in, const int* in_sizes, int n_in,
                              void* d_out, int out_size) {
    const float* x       = (const float*)d_in[0];
    const int*   ei      = (const int*)  d_in[1];
    const float* ea      = (const float*)d_in[2];
    // d_in[3] = bs (constant 128, hardcoded)
    const float* gconv_w = (const float*)d_in[4];
    const float* w_ih    = (const float*)d_in[5];
    const float* w_hh    = (const float*)d_in[6];
    const float* b_ih    = (const float*)d_in[7];
    const float* b_hh    = (const float*)d_in[8];
    const float* conv_w  = (const float*)d_in[9];
    const float* conv_b  = (const float*)d_in[10];
    const float* lin1_w  = (const float*)d_in[11];
    const float* lin1_b  = (const float*)d_in[12];
    const float* lin2_w  = (const float*)d_in[13];
    const float* lin2_b  = (const float*)d_in[14];
    float* out = (float*)d_out;

    float *ph, *pm, *pagg, *pgi, *pgh, *pwT;
    cudaGetSymbolAddress((void**)&ph,   g_h);
    cudaGetSymbolAddress((void**)&pm,   g_m);
    cudaGetSymbolAddress((void**)&pagg, g_agg);
    cudaGetSymbolAddress((void**)&pgi,  g_gi);
    cudaGetSymbolAddress((void**)&pgh,  g_gh);
    cudaGetSymbolAddress((void**)&pwT,  g_wT);

    cudaFuncSetAttribute(gemm_tf32, cudaFuncAttributeMaxDynamicSharedMemorySize, GEMM_SMEM);

    prep_gconv<<<(2 * HDIM * HDIM + 255) / 256, 256>>>(gconv_w, pwT);
    pad_kernel<<<(N_NODES * 32 + 255) / 256, 256>>>(x, ph);

    for (int layer = 0; layer < 2; layer++) {
        // m = h @ gconv_w[layer]  (B = transposed gconv weights, [n][k])
        gemm_tf32<<<dim3(N_NODES / 128, 1), 256, GEMM_SMEM>>>(
            ph, pwT + (size_t)layer * HDIM * HDIM, nullptr, pm, HDIM);
        // agg = 0
        zero_kernel<<<(N_NODES * 32 + 255) / 256, 256>>>((float4*)pagg, N_NODES * 32);
        // agg[dst] += m[src] * ea
        scatter_kernel<<<(N_EDGES * 32) / 256, 256>>>(ei, ea, pm, pagg);
        // gi = agg @ w_ih^T + b_ih ; gh = h @ w_hh^T + b_hh  (weights already [N,K])
        gemm_tf32<<<dim3(N_NODES / 128, 3), 256, GEMM_SMEM>>>(pagg, w_ih, b_ih, pgi, 384);
        gemm_tf32<<<dim3(N_NODES / 128, 3), 256, GEMM_SMEM>>>(ph,   w_hh, b_hh, pgh, 384);
        // GRU update
        gru_kernel<<<(N_NODES * 32 + 255) / 256, 256>>>(
            (const float4*)pgi, (const float4*)pgh, (float4*)ph);
    }

    post_kernel<<<BSZ, 256>>>(ph, conv_w, conv_b, lin1_w, lin1_b, lin2_w, lin2_b, out);
}